// round 17
// baseline (speedup 1.0000x reference)
#include <cuda_runtime.h>
#include <cuda_fp16.h>

#define N_LABELS 30000
#define HIDDEN   1024
#define BATCH    256
#define N_EDGES  (N_LABELS - 1)
#define CHUNK    8                  /* rec edges per block-level steal (512-thr CTA) */
#define BCE_BLOCKS BATCH            /* 256 blocks, 1 row each */
#define GRID_TOTAL 304              /* 2 CTAs per SM on 152 SMs */
#define NTHREADS   512

#define REC_PENALTY   1e-4
#define PROBA_PENALTY 1e-4

// ---------------- device scratch (zero-initialized at module load) ----------------
__device__ double g_acc_bce;
__device__ double g_acc_rec;
__device__ double g_acc_prob;
__device__ int    g_ctr;
__device__ int    g_done;

// ---------------- helpers ----------------
__device__ __forceinline__ float block_reduce_sum(float v) {
    __shared__ float red[16];
    int lane = threadIdx.x & 31;
    int wid  = threadIdx.x >> 5;          // 16 warps
    #pragma unroll
    for (int o = 16; o > 0; o >>= 1) v += __shfl_down_sync(0xffffffffu, v, o);
    if (lane == 0) red[wid] = v;
    __syncthreads();
    v = (threadIdx.x < 16) ? red[threadIdx.x] : 0.0f;
    if (wid == 0) {
        #pragma unroll
        for (int o = 8; o > 0; o >>= 1) v += __shfl_down_sync(0xffffffffu, v, o);
    }
    __syncthreads();
    return v;   // valid in thread 0
}

// half2 BCE + sigmoid for 2 elements: term = max(l,0)+log(1+e^-|l|)-l*t,
// sig = (l>=0 ? 1 : z)/(1+z). 3 MUFU per 2 elems.
__device__ __forceinline__ void bce2(__half2 l2, __half2 t2,
                                     __half2& term, __half2& sig) {
    const __half2 one  = __float2half2_rn(1.0f);
    const __half2 zero = __float2half2_rn(0.0f);
    __half2 z   = h2exp(__hneg2(__habs2(l2)));    // e^{-|l|} in (0,1]
    __half2 opz = __hadd2(one, z);                // 1+z
    term = __hsub2(__hadd2(__hmax2(l2, zero), h2log(opz)), __hmul2(l2, t2));
    __half2 ge  = __hge2(l2, zero);               // 1.0 / 0.0 per lane
    __half2 sel = __hfma2(ge, __hsub2(one, z), z);// l>=0 ? 1 : z
    sig = __hmul2(sel, h2rcp(opz));
}

__device__ __forceinline__ float rec_edge_term(float4 a, float4 b) {
    float d, s;
    d = a.x - b.x; s  = d * d;
    d = a.y - b.y; s += d * d;
    d = a.z - b.z; s += d * d;
    d = a.w - b.w; s += d * d;
    return s;
}

// ---------------- single fused kernel ----------------
// Blocks [0,256): BCE + prob_reg for row bid (fp16 sigmoid cache, 60 KB smem ->
// 2 CTAs/SM, 64 warps), then join rec work-stealing.
// Blocks [256,304): rec work-stealing immediately.
// rec: block-level CHUNK=8 steals, double-buffered base, one 16-warp barrier per
// chunk; the co-resident CTA hides the sync bubble.
__global__ __launch_bounds__(NTHREADS, 2)
void fused_kernel(const float* __restrict__ logits,
                  const float* __restrict__ targets,
                  const float* __restrict__ params,
                  const int*   __restrict__ par_i,   // raw index bytes (int32 view)
                  const int*   __restrict__ chi_i,
                  float* __restrict__ out) {
    extern __shared__ __half sigh[];     // N_LABELS halves = 60000 B
    __shared__ int s_base[2];
    __shared__ int s_mul;
    const int tid = threadIdx.x;
    const int bid = blockIdx.x;

    // ---- parallel index-dtype detection: 32 lanes, one 8B word each.
    // int64: every word < 30000. int32: word combines two random indices -> huge.
    if (tid < 32) {
        unsigned long long v = ((const unsigned long long*)par_i)[tid];
        unsigned big = __ballot_sync(0xffffffffu, v >= (unsigned long long)N_LABELS);
        if (tid == 0) s_mul = (big == 0u) ? 2 : 1;  // int64: low word at int-offset 2*i
    }
    __syncthreads();
    const int mul = s_mul;

    if (bid < BCE_BLOCKS) {
        const float4* lr = (const float4*)(logits  + (size_t)bid * N_LABELS);
        const float4* tr = (const float4*)(targets + (size_t)bid * N_LABELS);

        // Phase 1: BCE partials + fp16 sigmoid cache (evict-first stream).
        float bacc = 0.0f;
        for (int n4 = tid; n4 < N_LABELS / 4; n4 += NTHREADS) {
            float4 l = __ldcs(lr + n4);
            float4 t = __ldcs(tr + n4);
            __half2 t01, t23, s01, s23;
            bce2(__floats2half2_rn(l.x, l.y), __floats2half2_rn(t.x, t.y), t01, s01);
            bce2(__floats2half2_rn(l.z, l.w), __floats2half2_rn(t.z, t.w), t23, s23);
            uint2 o;
            o.x = *reinterpret_cast<unsigned*>(&s01);
            o.y = *reinterpret_cast<unsigned*>(&s23);
            ((uint2*)sigh)[n4] = o;                 // 4 halves per float4
            __half2 hs = __hadd2(t01, t23);
            float2 fs = __half22float2(hs);
            bacc += fs.x + fs.y;
        }
        __syncthreads();

        // Phase 2: prob_reg gathers from smem. 58 guard-free iterations + tail.
        // (tid + 57*512 <= 511 + 29184 = 29695 < N_EDGES)
        float pacc = 0.0f;
        #pragma unroll 4
        for (int i = 0; i < 58; i++) {
            int e = tid + i * NTHREADS;
            int pi = __ldg(par_i + (size_t)e * mul);
            int ci = __ldg(chi_i + (size_t)e * mul);
            float p = __half2float(sigh[pi]);
            float c = __half2float(sigh[ci]);
            pacc += fmaxf(c - p, 0.0f);
        }
        {   // tail
            int e = tid + 58 * NTHREADS;
            if (e < N_EDGES) {
                int pi = __ldg(par_i + (size_t)e * mul);
                int ci = __ldg(chi_i + (size_t)e * mul);
                float p = __half2float(sigh[pi]);
                float c = __half2float(sigh[ci]);
                pacc += fmaxf(c - p, 0.0f);
            }
        }

        float bsum = block_reduce_sum(bacc);
        float psum = block_reduce_sum(pacc);
        if (tid == 0) {
            atomicAdd(&g_acc_bce,  (double)bsum);
            atomicAdd(&g_acc_prob, (double)psum);
        }
    }

    // ---- rec_reg: block-level work stealing, CHUNK=8, 2 groups x 4 edges.
    // Double-buffered s_base -> one barrier per chunk. Indices preloaded so the
    // 8 float4 row loads batch (high MLP).
    const float4* P4 = (const float4*)params;
    const int g = tid >> 8;      // group (0..1)
    const int x = tid & 255;     // float4 index within the 1024-float row
    float racc = 0.0f;

    if (tid == 0) s_base[0] = atomicAdd(&g_ctr, CHUNK);
    __syncthreads();

    int parity = 0;
    for (;;) {
        const int base = s_base[parity];
        if (base >= N_EDGES) break;
        if (tid == 0) s_base[parity ^ 1] = atomicAdd(&g_ctr, CHUNK);

        int ip[4], ic[4];
        if (base + CHUNK <= N_EDGES) {           // block-uniform fast path
            #pragma unroll
            for (int k = 0; k < 4; k++) {
                int e = base + k * 2 + g;
                ip[k] = __ldg(par_i + (size_t)e * mul);
                ic[k] = __ldg(chi_i + (size_t)e * mul);
            }
        } else {                                  // single crossing chunk
            #pragma unroll
            for (int k = 0; k < 4; k++) {
                int e = base + k * 2 + g;
                bool ok = e < N_EDGES;
                ip[k] = ok ? __ldg(par_i + (size_t)e * mul) : 0;
                ic[k] = ok ? __ldg(chi_i + (size_t)e * mul) : 0;
            }
        }

        #pragma unroll
        for (int k = 0; k < 4; k++) {
            float4 a = __ldg(P4 + (size_t)ip[k] * (HIDDEN / 4) + x);
            float4 b = __ldg(P4 + (size_t)ic[k] * (HIDDEN / 4) + x);
            racc += rec_edge_term(a, b);
        }

        __syncthreads();        // next iteration reads the freshly written slot
        parity ^= 1;
    }

    float rsum = block_reduce_sum(racc);
    if (tid == 0) {
        atomicAdd(&g_acc_rec, (double)rsum);
        __threadfence();
        int prev = atomicAdd(&g_done, 1);
        if (prev == GRID_TOTAL - 1) {
            double acc_b = atomicAdd(&g_acc_bce,  0.0);  // L2-coherent reads
            double acc_r = atomicAdd(&g_acc_rec,  0.0);
            double acc_p = atomicAdd(&g_acc_prob, 0.0);
            double bce = acc_b / ((double)BATCH * (double)N_LABELS);
            out[0] = (float)(bce + REC_PENALTY * (0.5 * acc_r)
                                 + PROBA_PENALTY * acc_p);
            // reset for next graph replay
            g_acc_bce = 0.0; g_acc_rec = 0.0; g_acc_prob = 0.0;
            g_ctr = 0; g_done = 0;
        }
    }
}

// ---------------- launch ----------------
extern "C" void kernel_launch(void* const* d_in, const int* in_sizes, int n_in,
                              void* d_out, int out_size) {
    const float* logits  = (const float*)d_in[0];
    const float* targets = (const float*)d_in[1];
    const float* params  = (const float*)d_in[2];
    const int*   par_raw = (const int*)d_in[3];
    const int*   chi_raw = (const int*)d_in[4];
    float* out = (float*)d_out;

    static bool attr_set = false;
    if (!attr_set) {
        cudaFuncSetAttribute(fused_kernel,
                             cudaFuncAttributeMaxDynamicSharedMemorySize,
                             N_LABELS * (int)sizeof(__half));
        attr_set = true;
    }

    fused_kernel<<<GRID_TOTAL, NTHREADS, N_LABELS * sizeof(__half)>>>(
        logits, targets, params, par_raw, chi_raw, out);
}